// round 11
// baseline (speedup 1.0000x reference)
#include <cuda_runtime.h>
#include <math.h>

#define B_TOTAL 16384
#define PI_F 3.14159265358979323846f

typedef unsigned long long u64;

// ---------------- packed f32x2 helpers (exact fp32, 2 per issue) ----------------
__device__ __forceinline__ u64 pk(float lo, float hi) {
    u64 d; asm("mov.b64 %0, {%1, %2};" : "=l"(d) : "f"(lo), "f"(hi)); return d;
}
__device__ __forceinline__ void upk(u64 v, float& lo, float& hi) {
    asm("mov.b64 {%0, %1}, %2;" : "=f"(lo), "=f"(hi) : "l"(v));
}
__device__ __forceinline__ u64 f2fma(u64 a, u64 b, u64 c) {
    u64 d; asm("fma.rn.f32x2 %0, %1, %2, %3;" : "=l"(d) : "l"(a), "l"(b), "l"(c)); return d;
}
__device__ __forceinline__ u64 f2mul(u64 a, u64 b) {
    u64 d; asm("mul.rn.f32x2 %0, %1, %2;" : "=l"(d) : "l"(a), "l"(b)); return d;
}

// ---------------- scratch ----------------
__device__ float g_ang[10 * 16];
__device__ float g_cpost[10 * 32];
__device__ int   g_cls[B_TOTAL];
__device__ float g_qf[B_TOTAL * 256];

__device__ __forceinline__ float lrelu(float x) { return x > 0.f ? x : 0.2f * x; }

// ---------------- Kernel A1: per-class tables ----------------
__global__ void tables_kernel(const float* __restrict__ W1, const float* __restrict__ b1,
                              const float* __restrict__ W2, const float* __restrict__ b2,
                              const float* __restrict__ Wa, const float* __restrict__ ba,
                              const float* __restrict__ Wp1, const float* __restrict__ bp1,
                              const float* __restrict__ Wp2, const float* __restrict__ bp2)
{
    __shared__ float h[64], p1[32];
    int t = threadIdx.x;
    for (int c = 0; c < 10; c++) {
        float hv = 0.f;
        if (t < 64) { hv = lrelu(W1[t * 10 + c] + b1[t]); h[t] = hv; }
        __syncthreads();
        float acc = 0.f;
        if (t < 64) {
            acc = b2[t];
            for (int k = 0; k < 64; k++) acc = fmaf(W2[t * 64 + k], h[k], acc);
            acc = lrelu(acc);
        }
        __syncthreads();
        if (t < 64) h[t] = hv + acc;
        if (t < 32) p1[t] = lrelu(Wp1[t * 10 + c] + bp1[t]);
        __syncthreads();
        if (t < 16) {
            float a = ba[t];
            for (int k = 0; k < 64; k++) a = fmaf(Wa[t * 64 + k], h[k], a);
            g_ang[c * 16 + t] = tanhf(a) * PI_F;
        }
        if (t < 32) {
            float a = bp2[t];
            for (int k = 0; k < 32; k++) a = fmaf(Wp2[t * 32 + k], p1[k], a);
            g_cpost[c * 32 + t] = lrelu(a);
        }
        __syncthreads();
    }
}

// ---------------- Kernel A2: class ids ----------------
__global__ void class_kernel(const float* __restrict__ labels)
{
    int b = blockIdx.x * 256 + threadIdx.x;
    const float* l = labels + b * 10;
    int c = 0; float best = l[0];
#pragma unroll
    for (int j = 1; j < 10; j++) { float v = l[j]; if (v > best) { best = v; c = j; } }
    g_cls[b] = c;
}

// ---------------- Kernel B: qsim (warp/sample, 8 amps/lane, shear-form gates) ------
// Chunked: boff = block offset (each block = 8 samples).
__global__ __launch_bounds__(256) void qsim_kernel(const float* __restrict__ noise,
                                                   const float* __restrict__ qp,
                                                   int boff)
{
    __shared__ float2 cs[192];             // cos/sin of 0.5*w (for depth-0 folding)
    __shared__ float  ts[192];             // tan of 0.5*w (shear coefficients)
    __shared__ float  psi[8][8][2][2];     // base per-qubit vectors
    __shared__ float  psi2[8][8][2][2];    // per-gen rotated vectors
    int tid = threadIdx.x;
    if (tid < 192) {
        float w = qp[tid];
        float sw, cw; sincosf(0.5f * w, &sw, &cw);
        cs[tid] = make_float2(cw, sw);
        ts[tid] = sw / cw;
    }
    int warp = tid >> 5, lane = tid & 31;
    int b = (blockIdx.x + boff) * 8 + warp;
    __syncthreads();
    int c = g_cls[b];
    if (lane < 8) {
        // RZ(theta) * RY(ang + noise) |0>
        float t = 0.5f * (g_ang[c * 16 + lane] + noise[b * 8 + lane]);
        float st, ct; sincosf(t, &st, &ct);
        float th = 0.5f * g_ang[c * 16 + 8 + lane];
        float sth, cth; sincosf(th, &sth, &cth);
        psi[warp][lane][0][0] = ct * cth;
        psi[warp][lane][0][1] = -ct * sth;
        psi[warp][lane][1][0] = st * cth;
        psi[warp][lane][1][1] = st * sth;
    }
    // CZ-chain sign mask
    unsigned M = 0;
#pragma unroll
    for (int j = 0; j < 8; j++) {
        int idx = lane * 8 + j;
        M |= ((unsigned)(__popc(idx & (idx >> 1) & 0x7F) & 1)) << j;
    }
    __syncwarp();

    for (int g = 0; g < 4; g++) {
        // fold depth-0 RY into per-qubit vectors (product state, exact rotation)
        if (lane < 8) {
            float2 w0 = cs[g * 48 + lane];
            float cg = w0.x, sg = w0.y;
            float v0r = psi[warp][lane][0][0], v0i = psi[warp][lane][0][1];
            float v1r = psi[warp][lane][1][0], v1i = psi[warp][lane][1][1];
            psi2[warp][lane][0][0] = cg * v0r - sg * v1r;
            psi2[warp][lane][0][1] = cg * v0i - sg * v1i;
            psi2[warp][lane][1][0] = sg * v0r + cg * v1r;
            psi2[warp][lane][1][1] = sg * v0i + cg * v1i;
        }
        __syncwarp();

        // expand product state
        float br = 1.f, bi = 0.f;
#pragma unroll
        for (int k = 0; k < 5; k++) {
            int bit = (lane >> (4 - k)) & 1;
            float pr = psi2[warp][k][bit][0], pi = psi2[warp][k][bit][1];
            float nr = br * pr - bi * pi;
            float ni = br * pi + bi * pr;
            br = nr; bi = ni;
        }
        float qr[4], qi[4];
#pragma unroll
        for (int b6 = 0; b6 < 2; b6++)
#pragma unroll
            for (int b7 = 0; b7 < 2; b7++) {
                float xr = psi2[warp][6][b6][0], xi = psi2[warp][6][b6][1];
                float yr = psi2[warp][7][b7][0], yi = psi2[warp][7][b7][1];
                qr[b6 * 2 + b7] = xr * yr - xi * yi;
                qi[b6 * 2 + b7] = xr * yi + xi * yr;
            }
        float b5r[2], b5i[2];
#pragma unroll
        for (int b5 = 0; b5 < 2; b5++) {
            float pr = psi2[warp][5][b5][0], pi = psi2[warp][5][b5][1];
            b5r[b5] = br * pr - bi * pi;
            b5i[b5] = br * pi + bi * pr;
        }
        u64 a[8];
#pragma unroll
        for (int j = 0; j < 8; j++) {
            int b5 = (j >> 2) & 1, q67 = j & 3;
            float arj = b5r[b5] * qr[q67] - b5i[b5] * qi[q67];
            float aij = b5r[b5] * qi[q67] + b5i[b5] * qr[q67];
            a[j] = pk(arj, aij);
            if (M & (1u << j)) a[j] ^= 0x8000000080000000ULL;  // depth-0 CZ
        }

        // depths 1..5: shear form (global cos product cancels in epilogue)
        for (int d = 1; d < 6; d++) {
            const float* tsd = &ts[g * 48 + d * 8];
            // wires 0..4: cross-lane, 1 f2fma per amp
            for (int w = 0; w < 5; w++) {
                float tv = tsd[w];
                int m = 16 >> w;
                float sg = (lane & m) ? tv : -tv;
                u64 sgp = pk(sg, sg);
#pragma unroll
                for (int j = 0; j < 8; j++) {
                    u64 part = __shfl_xor_sync(0xffffffffu, a[j], m);
                    a[j] = f2fma(sgp, part, a[j]);
                }
            }
            // wire 5: local bit 2 (pairs j, j+4)
            {
                float tv = tsd[5];
                u64 tp = pk(tv, tv), mtp = pk(-tv, -tv);
#pragma unroll
                for (int j0 = 0; j0 < 4; j0++) {
                    int j1 = j0 + 4;
                    u64 v0 = a[j0], v1 = a[j1];
                    a[j0] = f2fma(mtp, v1, v0);
                    a[j1] = f2fma(tp, v0, v1);
                }
            }
            // wire 6: local bit 1 (pairs j, j+2)
            {
                float tv = tsd[6];
                u64 tp = pk(tv, tv), mtp = pk(-tv, -tv);
#pragma unroll
                for (int jj = 0; jj < 4; jj++) {
                    int j0 = (jj & 1) | ((jj & 2) << 1);  // 0,1,4,5
                    int j1 = j0 + 2;
                    u64 v0 = a[j0], v1 = a[j1];
                    a[j0] = f2fma(mtp, v1, v0);
                    a[j1] = f2fma(tp, v0, v1);
                }
            }
            // wire 7: local bit 0 (pairs j, j+1)
            {
                float tv = tsd[7];
                u64 tp = pk(tv, tv), mtp = pk(-tv, -tv);
#pragma unroll
                for (int j0 = 0; j0 < 8; j0 += 2) {
                    int j1 = j0 + 1;
                    u64 v0 = a[j0], v1 = a[j1];
                    a[j0] = f2fma(mtp, v1, v0);
                    a[j1] = f2fma(tp, v0, v1);
                }
            }
            if (d < 5) {
#pragma unroll
                for (int j = 0; j < 8; j++)
                    if (M & (1u << j)) a[j] ^= 0x8000000080000000ULL;
            }
        }

        // epilogue: probs[:64]/max(probs[:64]) (global sum AND global scale cancel)
        float p[8];
#pragma unroll
        for (int j = 0; j < 8; j++) {
            float r, i; upk(a[j], r, i);
            p[j] = fmaf(r, r, i * i);
        }
        float mx = p[0];
#pragma unroll
        for (int j = 1; j < 8; j++) mx = fmaxf(mx, p[j]);
        mx = fmaxf(mx, __shfl_xor_sync(0xffffffffu, mx, 4));
        mx = fmaxf(mx, __shfl_xor_sync(0xffffffffu, mx, 2));
        mx = fmaxf(mx, __shfl_xor_sync(0xffffffffu, mx, 1));
        if (lane < 8) {
            float inv = 1.f / mx;
            float* dst = &g_qf[b * 256 + g * 64 + lane * 8];
            float4 v0 = make_float4(p[0] * inv, p[1] * inv, p[2] * inv, p[3] * inv);
            float4 v1 = make_float4(p[4] * inv, p[5] * inv, p[6] * inv, p[7] * inv);
            *(float4*)dst = v0;
            *(float4*)(dst + 4) = v1;
        }
        __syncwarp();  // psi2 reused next gen
    }
}

// ---------------- Kernel C: fused MLP 288->128(LN)->128(LN)->64 tanh ----------------
// 64 samples/CTA, 512 threads (16 warps), 2 samples x 8 outputs per thread, f32x2.
// Chunked: coff = CTA offset.
#define XS_STRIDE 292
#define H_STRIDE  132
#define NS 64
#define MLP_THREADS 512
#define SMEM_C ((NS * XS_STRIDE + NS * H_STRIDE + 8192) * 4)

__global__ __launch_bounds__(MLP_THREADS) void mlp_kernel(
    const float* __restrict__ Wq1, const float* __restrict__ bq1,
    const float* __restrict__ g1,  const float* __restrict__ be1,
    const float* __restrict__ Wq2, const float* __restrict__ bq2,
    const float* __restrict__ g2,  const float* __restrict__ be2,
    const float* __restrict__ Wq3, const float* __restrict__ bq3,
    float* __restrict__ out, int coff)
{
    extern __shared__ float sm[];
    float* xs = sm;                         // 64 x 292 (reused as h2, stride 132)
    float* h1 = sm + NS * XS_STRIDE;        // 64 x 132
    float* wc = h1 + NS * H_STRIDE;         // 8192-float weight chunk
    int tid = threadIdx.x, warp = tid >> 5, lane = tid & 31;
    int b0 = (blockIdx.x + coff) * NS;
    int s1 = lane, s2 = lane + 32;

    for (int i = tid; i < NS * 64; i += MLP_THREADS) {
        int ss = i >> 6, k4 = (i & 63) << 2;
        *(float4*)&xs[ss * XS_STRIDE + k4] = *(const float4*)&g_qf[(b0 + ss) * 256 + k4];
    }
    for (int i = tid; i < NS * 8; i += MLP_THREADS) {
        int ss = i >> 3, k4 = (i & 7) << 2;
        *(float4*)&xs[ss * XS_STRIDE + 256 + k4] = *(const float4*)&g_cpost[g_cls[b0 + ss] * 32 + k4];
    }

    int ob = warp * 8;  // 16 warps x 8 outputs = 128
    // ---- layer 1: 288 -> 128 ----
    u64 aA[8], aB[8];
#pragma unroll
    for (int i = 0; i < 8; i++) { float bv = bq1[ob + i]; aA[i] = pk(bv, 0.f); aB[i] = pk(bv, 0.f); }
    for (int ch = 0; ch < 6; ch++) {
        __syncthreads();
        for (int i = tid * 4; i < 128 * 48; i += MLP_THREADS * 4) {
            int o = i / 48, kk = i % 48;
            *(float4*)&wc[i] = *(const float4*)&Wq1[o * 288 + ch * 48 + kk];
        }
        __syncthreads();
        const ulonglong2* xrA = (const ulonglong2*)&xs[s1 * XS_STRIDE + ch * 48];
        const ulonglong2* xrB = (const ulonglong2*)&xs[s2 * XS_STRIDE + ch * 48];
#pragma unroll
        for (int kk = 0; kk < 12; kk++) {
            ulonglong2 xa = xrA[kk], xb = xrB[kk];
#pragma unroll
            for (int i = 0; i < 8; i++) {
                ulonglong2 w = ((const ulonglong2*)&wc[(ob + i) * 48])[kk];
                aA[i] = f2fma(w.x, xa.x, aA[i]);
                aA[i] = f2fma(w.y, xa.y, aA[i]);
                aB[i] = f2fma(w.x, xb.x, aB[i]);
                aB[i] = f2fma(w.y, xb.y, aB[i]);
            }
        }
    }
    __syncthreads();
#pragma unroll
    for (int i = 0; i < 8; i++) {
        float lo, hi;
        upk(aA[i], lo, hi); h1[s1 * H_STRIDE + ob + i] = lrelu(lo + hi);
        upk(aB[i], lo, hi); h1[s2 * H_STRIDE + ob + i] = lrelu(lo + hi);
    }
    __syncthreads();

    // ---- LN1 (16 warps x 4 samples) ----
    {
        float gv[4], bev[4];
#pragma unroll
        for (int r = 0; r < 4; r++) { gv[r] = g1[lane + 32 * r]; bev[r] = be1[lane + 32 * r]; }
        int s0 = warp * 4;
        for (int ss = s0; ss < s0 + 4; ss++) {
            float v[4]; float sum = 0.f, sq = 0.f;
#pragma unroll
            for (int r = 0; r < 4; r++) {
                v[r] = h1[ss * H_STRIDE + lane + 32 * r];
                sum += v[r]; sq = fmaf(v[r], v[r], sq);
            }
#pragma unroll
            for (int off = 16; off; off >>= 1) {
                sum += __shfl_xor_sync(0xffffffffu, sum, off);
                sq  += __shfl_xor_sync(0xffffffffu, sq, off);
            }
            float mu = sum * (1.f / 128.f);
            float var = sq * (1.f / 128.f) - mu * mu;
            float rs = rsqrtf(var + 1e-5f);
#pragma unroll
            for (int r = 0; r < 4; r++)
                h1[ss * H_STRIDE + lane + 32 * r] = (v[r] - mu) * rs * gv[r] + bev[r];
        }
    }
    __syncthreads();

    // ---- layer 2: 128 -> 128 ----
    float* h2 = xs;  // reuse, stride H_STRIDE
#pragma unroll
    for (int i = 0; i < 8; i++) { float bv = bq2[ob + i]; aA[i] = pk(bv, 0.f); aB[i] = pk(bv, 0.f); }
    for (int ch = 0; ch < 2; ch++) {
        __syncthreads();
        for (int i = tid * 4; i < 128 * 64; i += MLP_THREADS * 4) {
            int o = i >> 6, kk = i & 63;
            *(float4*)&wc[i] = *(const float4*)&Wq2[o * 128 + ch * 64 + kk];
        }
        __syncthreads();
        const ulonglong2* xrA = (const ulonglong2*)&h1[s1 * H_STRIDE + ch * 64];
        const ulonglong2* xrB = (const ulonglong2*)&h1[s2 * H_STRIDE + ch * 64];
#pragma unroll
        for (int kk = 0; kk < 16; kk++) {
            ulonglong2 xa = xrA[kk], xb = xrB[kk];
#pragma unroll
            for (int i = 0; i < 8; i++) {
                ulonglong2 w = ((const ulonglong2*)&wc[(ob + i) * 64])[kk];
                aA[i] = f2fma(w.x, xa.x, aA[i]);
                aA[i] = f2fma(w.y, xa.y, aA[i]);
                aB[i] = f2fma(w.x, xb.x, aB[i]);
                aB[i] = f2fma(w.y, xb.y, aB[i]);
            }
        }
    }
    __syncthreads();
#pragma unroll
    for (int i = 0; i < 8; i++) {
        float lo, hi;
        upk(aA[i], lo, hi); h2[s1 * H_STRIDE + ob + i] = lrelu(lo + hi);
        upk(aB[i], lo, hi); h2[s2 * H_STRIDE + ob + i] = lrelu(lo + hi);
    }
    __syncthreads();

    // ---- LN2 ----
    {
        float gv[4], bev[4];
#pragma unroll
        for (int r = 0; r < 4; r++) { gv[r] = g2[lane + 32 * r]; bev[r] = be2[lane + 32 * r]; }
        int s0 = warp * 4;
        for (int ss = s0; ss < s0 + 4; ss++) {
            float v[4]; float sum = 0.f, sq = 0.f;
#pragma unroll
            for (int r = 0; r < 4; r++) {
                v[r] = h2[ss * H_STRIDE + lane + 32 * r];
                sum += v[r]; sq = fmaf(v[r], v[r], sq);
            }
#pragma unroll
            for (int off = 16; off; off >>= 1) {
                sum += __shfl_xor_sync(0xffffffffu, sum, off);
                sq  += __shfl_xor_sync(0xffffffffu, sq, off);
            }
            float mu = sum * (1.f / 128.f);
            float var = sq * (1.f / 128.f) - mu * mu;
            float rs = rsqrtf(var + 1e-5f);
#pragma unroll
            for (int r = 0; r < 4; r++)
                h2[ss * H_STRIDE + lane + 32 * r] = (v[r] - mu) * rs * gv[r] + bev[r];
        }
    }

    // ---- layer 3: 128 -> 64, tanh ----
    int ob3 = warp * 4;  // 16 warps x 4 outputs = 64
    u64 cA[4], cB[4];
#pragma unroll
    for (int i = 0; i < 4; i++) { float bv = bq3[ob3 + i]; cA[i] = pk(bv, 0.f); cB[i] = pk(bv, 0.f); }
    __syncthreads();
    for (int i = tid * 4; i < 64 * 128; i += MLP_THREADS * 4)
        *(float4*)&wc[i] = *(const float4*)&Wq3[i];
    __syncthreads();
    {
        const ulonglong2* xrA = (const ulonglong2*)&h2[s1 * H_STRIDE];
        const ulonglong2* xrB = (const ulonglong2*)&h2[s2 * H_STRIDE];
#pragma unroll
        for (int kk = 0; kk < 32; kk++) {
            ulonglong2 xa = xrA[kk], xb = xrB[kk];
#pragma unroll
            for (int i = 0; i < 4; i++) {
                ulonglong2 w = ((const ulonglong2*)&wc[(ob3 + i) * 128])[kk];
                cA[i] = f2fma(w.x, xa.x, cA[i]);
                cA[i] = f2fma(w.y, xa.y, cA[i]);
                cB[i] = f2fma(w.x, xb.x, cB[i]);
                cB[i] = f2fma(w.y, xb.y, cB[i]);
            }
        }
    }
    {
        float oA[4], oB[4];
#pragma unroll
        for (int i = 0; i < 4; i++) {
            float lo, hi;
            upk(cA[i], lo, hi); oA[i] = tanhf(lo + hi);
            upk(cB[i], lo, hi); oB[i] = tanhf(lo + hi);
        }
        *(float4*)&out[(b0 + s1) * 64 + ob3] = make_float4(oA[0], oA[1], oA[2], oA[3]);
        *(float4*)&out[(b0 + s2) * 64 + ob3] = make_float4(oB[0], oB[1], oB[2], oB[3]);
    }
}

// ---------------- launch: 4-chunk software pipeline across 2 streams ----------------
#define NCHUNK 4
#define QBLK_PER_CHUNK 512   // 512 blocks x 8 samples = 4096 samples
#define MBLK_PER_CHUNK 64    // 64 CTAs x 64 samples = 4096 samples

extern "C" void kernel_launch(void* const* d_in, const int* in_sizes, int n_in,
                              void* d_out, int out_size)
{
    const float* noise  = (const float*)d_in[0];
    const float* labels = (const float*)d_in[1];
    const float* qp     = (const float*)d_in[2];
    const float* W1  = (const float*)d_in[3];
    const float* b1  = (const float*)d_in[4];
    const float* W2  = (const float*)d_in[5];
    const float* b2  = (const float*)d_in[6];
    const float* Wa  = (const float*)d_in[7];
    const float* ba  = (const float*)d_in[8];
    const float* Wp1 = (const float*)d_in[9];
    const float* bp1 = (const float*)d_in[10];
    const float* Wp2 = (const float*)d_in[11];
    const float* bp2 = (const float*)d_in[12];
    const float* Wq1 = (const float*)d_in[13];
    const float* bq1 = (const float*)d_in[14];
    const float* g1  = (const float*)d_in[15];
    const float* be1 = (const float*)d_in[16];
    const float* Wq2 = (const float*)d_in[17];
    const float* bq2 = (const float*)d_in[18];
    const float* g2  = (const float*)d_in[19];
    const float* be2 = (const float*)d_in[20];
    const float* Wq3 = (const float*)d_in[21];
    const float* bq3 = (const float*)d_in[22];

    cudaFuncSetAttribute(mlp_kernel, cudaFuncAttributeMaxDynamicSharedMemorySize, SMEM_C);

    // Fresh side stream + events each call (host resources only, no device memory;
    // kernel_launch host code runs only for correctness + capture, not on replays).
    cudaStream_t s2;
    cudaStreamCreateWithFlags(&s2, cudaStreamNonBlocking);
    cudaEvent_t eq[NCHUNK], evDone;
    for (int i = 0; i < NCHUNK; i++) cudaEventCreateWithFlags(&eq[i], cudaEventDisableTiming);
    cudaEventCreateWithFlags(&evDone, cudaEventDisableTiming);

    tables_kernel<<<1, 64>>>(W1, b1, W2, b2, Wa, ba, Wp1, bp1, Wp2, bp2);
    class_kernel<<<64, 256>>>(labels);

    // s0: qsim chunks serially; event after each
    for (int c = 0; c < NCHUNK; c++) {
        qsim_kernel<<<QBLK_PER_CHUNK, 256>>>(noise, qp, c * QBLK_PER_CHUNK);
        cudaEventRecord(eq[c], 0);
    }
    // s2: mlp chunk c starts as soon as qsim chunk c is done (overlaps qsim c+1)
    for (int c = 0; c < NCHUNK; c++) {
        cudaStreamWaitEvent(s2, eq[c], 0);
        mlp_kernel<<<MBLK_PER_CHUNK, MLP_THREADS, SMEM_C, s2>>>(
            Wq1, bq1, g1, be1, Wq2, bq2, g2, be2, Wq3, bq3,
            (float*)d_out, c * MBLK_PER_CHUNK);
    }
    cudaEventRecord(evDone, s2);
    cudaStreamWaitEvent(0, evDone, 0);   // join side stream back into capture stream
}

// round 12
// speedup vs baseline: 1.2718x; 1.2718x over previous
#include <cuda_runtime.h>
#include <math.h>

#define B_TOTAL 16384
#define PI_F 3.14159265358979323846f

typedef unsigned long long u64;

// ---------------- packed f32x2 helpers (exact fp32, 2 per issue) ----------------
__device__ __forceinline__ u64 pk(float lo, float hi) {
    u64 d; asm("mov.b64 %0, {%1, %2};" : "=l"(d) : "f"(lo), "f"(hi)); return d;
}
__device__ __forceinline__ void upk(u64 v, float& lo, float& hi) {
    asm("mov.b64 {%0, %1}, %2;" : "=f"(lo), "=f"(hi) : "l"(v));
}
__device__ __forceinline__ u64 f2fma(u64 a, u64 b, u64 c) {
    u64 d; asm("fma.rn.f32x2 %0, %1, %2, %3;" : "=l"(d) : "l"(a), "l"(b), "l"(c)); return d;
}

// ---------------- scratch ----------------
__device__ float g_ang[10 * 16];
__device__ float g_cpost[10 * 32];
__device__ int   g_cls[B_TOTAL];
__device__ float g_qf[B_TOTAL * 256];

__device__ __forceinline__ float lrelu(float x) { return x > 0.f ? x : 0.2f * x; }

// ---------------- Kernel A1: per-class tables ----------------
__global__ void tables_kernel(const float* __restrict__ W1, const float* __restrict__ b1,
                              const float* __restrict__ W2, const float* __restrict__ b2,
                              const float* __restrict__ Wa, const float* __restrict__ ba,
                              const float* __restrict__ Wp1, const float* __restrict__ bp1,
                              const float* __restrict__ Wp2, const float* __restrict__ bp2)
{
    __shared__ float h[64], p1[32];
    int t = threadIdx.x;
    for (int c = 0; c < 10; c++) {
        float hv = 0.f;
        if (t < 64) { hv = lrelu(W1[t * 10 + c] + b1[t]); h[t] = hv; }
        __syncthreads();
        float acc = 0.f;
        if (t < 64) {
            acc = b2[t];
            for (int k = 0; k < 64; k++) acc = fmaf(W2[t * 64 + k], h[k], acc);
            acc = lrelu(acc);
        }
        __syncthreads();
        if (t < 64) h[t] = hv + acc;
        if (t < 32) p1[t] = lrelu(Wp1[t * 10 + c] + bp1[t]);
        __syncthreads();
        if (t < 16) {
            float a = ba[t];
            for (int k = 0; k < 64; k++) a = fmaf(Wa[t * 64 + k], h[k], a);
            g_ang[c * 16 + t] = tanhf(a) * PI_F;
        }
        if (t < 32) {
            float a = bp2[t];
            for (int k = 0; k < 32; k++) a = fmaf(Wp2[t * 32 + k], p1[k], a);
            g_cpost[c * 32 + t] = lrelu(a);
        }
        __syncthreads();
    }
}

// ---------------- Kernel A2: class ids ----------------
__global__ void class_kernel(const float* __restrict__ labels)
{
    int b = blockIdx.x * 256 + threadIdx.x;
    const float* l = labels + b * 10;
    int c = 0; float best = l[0];
#pragma unroll
    for (int j = 1; j < 10; j++) { float v = l[j]; if (v > best) { best = v; c = j; } }
    g_cls[b] = c;
}

// ---------------- Kernel B: qsim, 2 samples/warp, 16 lanes/sample, 16 amps/lane ----
// lane = s*16 + L. Amp idx = L*16 + j, wire w <-> bit (7-w) of idx.
// Wires 0..3 -> L bits 3..0 (shfl masks 8,4,2,1). Wires 4..7 -> j bits 3..0 (local).
// Depth-0 RY folded into per-qubit vectors; state re-expanded per generator
// (no smem amp state). Depths 1..5 in shear form (global cos product cancels
// in the probs/max epilogue). CZ chain = sign-bit XOR; final CZ skipped.
__global__ __launch_bounds__(256) void qsim_kernel(const float* __restrict__ noise,
                                                   const float* __restrict__ qp)
{
    __shared__ float2 cs[192];             // cos/sin 0.5*w (depth-0 fold)
    __shared__ float  ts[192];             // tan 0.5*w (shear coefficients)
    __shared__ float  psi[16][8][2][2];    // base per-qubit vectors (16 samples/CTA)
    __shared__ float  psi2[16][8][2][2];   // per-gen rotated vectors
    int tid = threadIdx.x;
    if (tid < 192) {
        float w = qp[tid];
        float sw, cw; sincosf(0.5f * w, &sw, &cw);
        cs[tid] = make_float2(cw, sw);
        ts[tid] = sw / cw;
    }
    int warp = tid >> 5, lane = tid & 31;
    int s = lane >> 4, L = lane & 15;
    int sl = warp * 2 + s;
    int b = blockIdx.x * 16 + sl;

    if (tid < 128) {   // one thread per (sample, qubit): RZ(theta)*RY(ang+noise)|0>
        int slq = tid >> 3, q = tid & 7;
        int bb = blockIdx.x * 16 + slq;
        int c = g_cls[bb];
        float t = 0.5f * (g_ang[c * 16 + q] + noise[bb * 8 + q]);
        float st, ct; sincosf(t, &st, &ct);
        float th = 0.5f * g_ang[c * 16 + 8 + q];
        float sth, cth; sincosf(th, &sth, &cth);
        psi[slq][q][0][0] = ct * cth;
        psi[slq][q][0][1] = -ct * sth;
        psi[slq][q][1][0] = st * cth;
        psi[slq][q][1][1] = st * sth;
    }
    __syncthreads();

    // CZ-chain sign mask: bit j = parity(popc(idx & idx>>1 & 0x7F)), idx = L*16+j
    unsigned M = 0;
#pragma unroll
    for (int j = 0; j < 16; j++) {
        int idx = L * 16 + j;
        M |= ((unsigned)(__popc(idx & (idx >> 1) & 0x7F) & 1)) << j;
    }

    for (int g = 0; g < 4; g++) {
        // fold depth-0 RY into per-qubit vectors (warp-local: lanes 0..15 cover
        // this warp's 2 samples x 8 qubits)
        if (lane < 16) {
            int s2 = lane >> 3, q = lane & 7;
            int slf = warp * 2 + s2;
            float2 w0 = cs[g * 48 + q];
            float cg = w0.x, sg = w0.y;
            float v0r = psi[slf][q][0][0], v0i = psi[slf][q][0][1];
            float v1r = psi[slf][q][1][0], v1i = psi[slf][q][1][1];
            psi2[slf][q][0][0] = cg * v0r - sg * v1r;
            psi2[slf][q][0][1] = cg * v0i - sg * v1i;
            psi2[slf][q][1][0] = sg * v0r + cg * v1r;
            psi2[slf][q][1][1] = sg * v0i + cg * v1i;
        }
        __syncwarp();

        // base over wires 0..3 (L bits 3..0)
        float br = 1.f, bi = 0.f;
#pragma unroll
        for (int w = 0; w < 4; w++) {
            int bit = (L >> (3 - w)) & 1;
            float pr = psi2[sl][w][bit][0], pi = psi2[sl][w][bit][1];
            float nr = br * pr - bi * pi;
            float ni = br * pi + bi * pr;
            br = nr; bi = ni;
        }
        // doubling over wires 7,6,5 (j bits 0,1,2) -> 8 intermediates
        float xr[8], xi[8];
        xr[0] = br; xi[0] = bi;
#pragma unroll
        for (int stage = 0; stage < 3; stage++) {
            int w = 7 - stage;
            int len = 1 << stage;
            float p0r = psi2[sl][w][0][0], p0i = psi2[sl][w][0][1];
            float p1r = psi2[sl][w][1][0], p1i = psi2[sl][w][1][1];
#pragma unroll
            for (int k = 0; k < 4; k++) {
                if (k < len) {
                    float t1r = xr[k] * p1r - xi[k] * p1i;
                    float t1i = xr[k] * p1i + xi[k] * p1r;
                    float t0r = xr[k] * p0r - xi[k] * p0i;
                    float t0i = xr[k] * p0i + xi[k] * p0r;
                    xr[k + len] = t1r; xi[k + len] = t1i;
                    xr[k] = t0r; xi[k] = t0i;
                }
            }
        }
        // wire 4 (j bit 3) applied at pack time: a[j]=x8[j]*p4[0], a[j+8]=x8[j]*p4[1]
        u64 a[16];
        {
            float p0r = psi2[sl][4][0][0], p0i = psi2[sl][4][0][1];
            float p1r = psi2[sl][4][1][0], p1i = psi2[sl][4][1][1];
#pragma unroll
            for (int j = 0; j < 8; j++) {
                a[j]     = pk(xr[j] * p0r - xi[j] * p0i, xr[j] * p0i + xi[j] * p0r);
                a[j + 8] = pk(xr[j] * p1r - xi[j] * p1i, xr[j] * p1i + xi[j] * p1r);
            }
        }
#pragma unroll
        for (int j = 0; j < 16; j++)
            if (M & (1u << j)) a[j] ^= 0x8000000080000000ULL;  // depth-0 CZ

        // depths 1..5: shear form
        for (int d = 1; d < 6; d++) {
            const float* tsd = &ts[g * 48 + d * 8];
            // wires 0..3: cross-lane, masks 8,4,2,1 (stay within 16-lane group)
#pragma unroll
            for (int w = 0; w < 4; w++) {
                float tv = tsd[w];
                int m = 8 >> w;
                float sg = (L & m) ? tv : -tv;
                u64 sgp = pk(sg, sg);
#pragma unroll
                for (int j = 0; j < 16; j++) {
                    u64 part = __shfl_xor_sync(0xffffffffu, a[j], m);
                    a[j] = f2fma(sgp, part, a[j]);
                }
            }
            // wire 4: step 8
            {
                float tv = tsd[4];
                u64 tp = pk(tv, tv), mtp = pk(-tv, -tv);
#pragma unroll
                for (int j0 = 0; j0 < 8; j0++) {
                    int j1 = j0 + 8;
                    u64 v0 = a[j0], v1 = a[j1];
                    a[j0] = f2fma(mtp, v1, v0);
                    a[j1] = f2fma(tp, v0, v1);
                }
            }
            // wire 5: step 4
            {
                float tv = tsd[5];
                u64 tp = pk(tv, tv), mtp = pk(-tv, -tv);
#pragma unroll
                for (int t = 0; t < 8; t++) {
                    int j0 = (t & 3) | ((t >> 2) << 3);   // 0,1,2,3,8,9,10,11
                    int j1 = j0 + 4;
                    u64 v0 = a[j0], v1 = a[j1];
                    a[j0] = f2fma(mtp, v1, v0);
                    a[j1] = f2fma(tp, v0, v1);
                }
            }
            // wire 6: step 2
            {
                float tv = tsd[6];
                u64 tp = pk(tv, tv), mtp = pk(-tv, -tv);
#pragma unroll
                for (int t = 0; t < 8; t++) {
                    int j0 = (t & 1) | ((t >> 1) << 2);   // 0,1,4,5,8,9,12,13
                    int j1 = j0 + 2;
                    u64 v0 = a[j0], v1 = a[j1];
                    a[j0] = f2fma(mtp, v1, v0);
                    a[j1] = f2fma(tp, v0, v1);
                }
            }
            // wire 7: step 1
            {
                float tv = tsd[7];
                u64 tp = pk(tv, tv), mtp = pk(-tv, -tv);
#pragma unroll
                for (int t = 0; t < 8; t++) {
                    int j0 = t << 1, j1 = j0 + 1;
                    u64 v0 = a[j0], v1 = a[j1];
                    a[j0] = f2fma(mtp, v1, v0);
                    a[j1] = f2fma(tp, v0, v1);
                }
            }
            if (d < 5) {
#pragma unroll
                for (int j = 0; j < 16; j++)
                    if (M & (1u << j)) a[j] ^= 0x8000000080000000ULL;
            }
        }

        // epilogue: p0 = idx<64 -> lanes L<4; normalize by max over those 64
        float p[16];
#pragma unroll
        for (int j = 0; j < 16; j++) {
            float r, i; upk(a[j], r, i);
            p[j] = fmaf(r, r, i * i);
        }
        float mx = p[0];
#pragma unroll
        for (int j = 1; j < 16; j++) mx = fmaxf(mx, p[j]);
        mx = fmaxf(mx, __shfl_xor_sync(0xffffffffu, mx, 1));
        mx = fmaxf(mx, __shfl_xor_sync(0xffffffffu, mx, 2));
        if (L < 4) {
            float inv = 1.f / mx;
            float* dst = &g_qf[b * 256 + g * 64 + L * 16];
#pragma unroll
            for (int j = 0; j < 16; j += 4)
                *(float4*)(dst + j) = make_float4(p[j] * inv, p[j + 1] * inv,
                                                 p[j + 2] * inv, p[j + 3] * inv);
        }
        __syncwarp();  // psi2 reused next gen
    }
}

// ---------------- Kernel C: fused MLP 288->128(LN)->128(LN)->64 tanh ----------------
// 64 samples/CTA, 512 threads (16 warps), 2 samples x 8 outputs per thread, f32x2.
#define XS_STRIDE 292
#define H_STRIDE  132
#define NS 64
#define MLP_THREADS 512
#define SMEM_C ((NS * XS_STRIDE + NS * H_STRIDE + 8192) * 4)

__global__ __launch_bounds__(MLP_THREADS) void mlp_kernel(
    const float* __restrict__ Wq1, const float* __restrict__ bq1,
    const float* __restrict__ g1,  const float* __restrict__ be1,
    const float* __restrict__ Wq2, const float* __restrict__ bq2,
    const float* __restrict__ g2,  const float* __restrict__ be2,
    const float* __restrict__ Wq3, const float* __restrict__ bq3,
    float* __restrict__ out)
{
    extern __shared__ float sm[];
    float* xs = sm;                         // 64 x 292 (reused as h2, stride 132)
    float* h1 = sm + NS * XS_STRIDE;        // 64 x 132
    float* wc = h1 + NS * H_STRIDE;         // 8192-float weight chunk
    int tid = threadIdx.x, warp = tid >> 5, lane = tid & 31;
    int b0 = blockIdx.x * NS;
    int s1 = lane, s2 = lane + 32;

    for (int i = tid; i < NS * 64; i += MLP_THREADS) {
        int ss = i >> 6, k4 = (i & 63) << 2;
        *(float4*)&xs[ss * XS_STRIDE + k4] = *(const float4*)&g_qf[(b0 + ss) * 256 + k4];
    }
    for (int i = tid; i < NS * 8; i += MLP_THREADS) {
        int ss = i >> 3, k4 = (i & 7) << 2;
        *(float4*)&xs[ss * XS_STRIDE + 256 + k4] = *(const float4*)&g_cpost[g_cls[b0 + ss] * 32 + k4];
    }

    int ob = warp * 8;  // 16 warps x 8 outputs = 128
    // ---- layer 1: 288 -> 128 ----
    u64 aA[8], aB[8];
#pragma unroll
    for (int i = 0; i < 8; i++) { float bv = bq1[ob + i]; aA[i] = pk(bv, 0.f); aB[i] = pk(bv, 0.f); }
    for (int ch = 0; ch < 6; ch++) {
        __syncthreads();
        for (int i = tid * 4; i < 128 * 48; i += MLP_THREADS * 4) {
            int o = i / 48, kk = i % 48;
            *(float4*)&wc[i] = *(const float4*)&Wq1[o * 288 + ch * 48 + kk];
        }
        __syncthreads();
        const ulonglong2* xrA = (const ulonglong2*)&xs[s1 * XS_STRIDE + ch * 48];
        const ulonglong2* xrB = (const ulonglong2*)&xs[s2 * XS_STRIDE + ch * 48];
#pragma unroll
        for (int kk = 0; kk < 12; kk++) {
            ulonglong2 xa = xrA[kk], xb = xrB[kk];
#pragma unroll
            for (int i = 0; i < 8; i++) {
                ulonglong2 w = ((const ulonglong2*)&wc[(ob + i) * 48])[kk];
                aA[i] = f2fma(w.x, xa.x, aA[i]);
                aA[i] = f2fma(w.y, xa.y, aA[i]);
                aB[i] = f2fma(w.x, xb.x, aB[i]);
                aB[i] = f2fma(w.y, xb.y, aB[i]);
            }
        }
    }
    __syncthreads();
#pragma unroll
    for (int i = 0; i < 8; i++) {
        float lo, hi;
        upk(aA[i], lo, hi); h1[s1 * H_STRIDE + ob + i] = lrelu(lo + hi);
        upk(aB[i], lo, hi); h1[s2 * H_STRIDE + ob + i] = lrelu(lo + hi);
    }
    __syncthreads();

    // ---- LN1 (16 warps x 4 samples) ----
    {
        float gv[4], bev[4];
#pragma unroll
        for (int r = 0; r < 4; r++) { gv[r] = g1[lane + 32 * r]; bev[r] = be1[lane + 32 * r]; }
        int s0 = warp * 4;
        for (int ss = s0; ss < s0 + 4; ss++) {
            float v[4]; float sum = 0.f, sq = 0.f;
#pragma unroll
            for (int r = 0; r < 4; r++) {
                v[r] = h1[ss * H_STRIDE + lane + 32 * r];
                sum += v[r]; sq = fmaf(v[r], v[r], sq);
            }
#pragma unroll
            for (int off = 16; off; off >>= 1) {
                sum += __shfl_xor_sync(0xffffffffu, sum, off);
                sq  += __shfl_xor_sync(0xffffffffu, sq, off);
            }
            float mu = sum * (1.f / 128.f);
            float var = sq * (1.f / 128.f) - mu * mu;
            float rs = rsqrtf(var + 1e-5f);
#pragma unroll
            for (int r = 0; r < 4; r++)
                h1[ss * H_STRIDE + lane + 32 * r] = (v[r] - mu) * rs * gv[r] + bev[r];
        }
    }
    __syncthreads();

    // ---- layer 2: 128 -> 128 ----
    float* h2 = xs;  // reuse, stride H_STRIDE
#pragma unroll
    for (int i = 0; i < 8; i++) { float bv = bq2[ob + i]; aA[i] = pk(bv, 0.f); aB[i] = pk(bv, 0.f); }
    for (int ch = 0; ch < 2; ch++) {
        __syncthreads();
        for (int i = tid * 4; i < 128 * 64; i += MLP_THREADS * 4) {
            int o = i >> 6, kk = i & 63;
            *(float4*)&wc[i] = *(const float4*)&Wq2[o * 128 + ch * 64 + kk];
        }
        __syncthreads();
        const ulonglong2* xrA = (const ulonglong2*)&h1[s1 * H_STRIDE + ch * 64];
        const ulonglong2* xrB = (const ulonglong2*)&h1[s2 * H_STRIDE + ch * 64];
#pragma unroll
        for (int kk = 0; kk < 16; kk++) {
            ulonglong2 xa = xrA[kk], xb = xrB[kk];
#pragma unroll
            for (int i = 0; i < 8; i++) {
                ulonglong2 w = ((const ulonglong2*)&wc[(ob + i) * 64])[kk];
                aA[i] = f2fma(w.x, xa.x, aA[i]);
                aA[i] = f2fma(w.y, xa.y, aA[i]);
                aB[i] = f2fma(w.x, xb.x, aB[i]);
                aB[i] = f2fma(w.y, xb.y, aB[i]);
            }
        }
    }
    __syncthreads();
#pragma unroll
    for (int i = 0; i < 8; i++) {
        float lo, hi;
        upk(aA[i], lo, hi); h2[s1 * H_STRIDE + ob + i] = lrelu(lo + hi);
        upk(aB[i], lo, hi); h2[s2 * H_STRIDE + ob + i] = lrelu(lo + hi);
    }
    __syncthreads();

    // ---- LN2 ----
    {
        float gv[4], bev[4];
#pragma unroll
        for (int r = 0; r < 4; r++) { gv[r] = g2[lane + 32 * r]; bev[r] = be2[lane + 32 * r]; }
        int s0 = warp * 4;
        for (int ss = s0; ss < s0 + 4; ss++) {
            float v[4]; float sum = 0.f, sq = 0.f;
#pragma unroll
            for (int r = 0; r < 4; r++) {
                v[r] = h2[ss * H_STRIDE + lane + 32 * r];
                sum += v[r]; sq = fmaf(v[r], v[r], sq);
            }
#pragma unroll
            for (int off = 16; off; off >>= 1) {
                sum += __shfl_xor_sync(0xffffffffu, sum, off);
                sq  += __shfl_xor_sync(0xffffffffu, sq, off);
            }
            float mu = sum * (1.f / 128.f);
            float var = sq * (1.f / 128.f) - mu * mu;
            float rs = rsqrtf(var + 1e-5f);
#pragma unroll
            for (int r = 0; r < 4; r++)
                h2[ss * H_STRIDE + lane + 32 * r] = (v[r] - mu) * rs * gv[r] + bev[r];
        }
    }

    // ---- layer 3: 128 -> 64, tanh ----
    int ob3 = warp * 4;  // 16 warps x 4 outputs = 64
    u64 cA[4], cB[4];
#pragma unroll
    for (int i = 0; i < 4; i++) { float bv = bq3[ob3 + i]; cA[i] = pk(bv, 0.f); cB[i] = pk(bv, 0.f); }
    __syncthreads();
    for (int i = tid * 4; i < 64 * 128; i += MLP_THREADS * 4)
        *(float4*)&wc[i] = *(const float4*)&Wq3[i];
    __syncthreads();
    {
        const ulonglong2* xrA = (const ulonglong2*)&h2[s1 * H_STRIDE];
        const ulonglong2* xrB = (const ulonglong2*)&h2[s2 * H_STRIDE];
#pragma unroll
        for (int kk = 0; kk < 32; kk++) {
            ulonglong2 xa = xrA[kk], xb = xrB[kk];
#pragma unroll
            for (int i = 0; i < 4; i++) {
                ulonglong2 w = ((const ulonglong2*)&wc[(ob3 + i) * 128])[kk];
                cA[i] = f2fma(w.x, xa.x, cA[i]);
                cA[i] = f2fma(w.y, xa.y, cA[i]);
                cB[i] = f2fma(w.x, xb.x, cB[i]);
                cB[i] = f2fma(w.y, xb.y, cB[i]);
            }
        }
    }
    {
        float oA[4], oB[4];
#pragma unroll
        for (int i = 0; i < 4; i++) {
            float lo, hi;
            upk(cA[i], lo, hi); oA[i] = tanhf(lo + hi);
            upk(cB[i], lo, hi); oB[i] = tanhf(lo + hi);
        }
        *(float4*)&out[(b0 + s1) * 64 + ob3] = make_float4(oA[0], oA[1], oA[2], oA[3]);
        *(float4*)&out[(b0 + s2) * 64 + ob3] = make_float4(oB[0], oB[1], oB[2], oB[3]);
    }
}

// ---------------- launch (serial, single stream) ----------------
extern "C" void kernel_launch(void* const* d_in, const int* in_sizes, int n_in,
                              void* d_out, int out_size)
{
    const float* noise  = (const float*)d_in[0];
    const float* labels = (const float*)d_in[1];
    const float* qp     = (const float*)d_in[2];
    const float* W1  = (const float*)d_in[3];
    const float* b1  = (const float*)d_in[4];
    const float* W2  = (const float*)d_in[5];
    const float* b2  = (const float*)d_in[6];
    const float* Wa  = (const float*)d_in[7];
    const float* ba  = (const float*)d_in[8];
    const float* Wp1 = (const float*)d_in[9];
    const float* bp1 = (const float*)d_in[10];
    const float* Wp2 = (const float*)d_in[11];
    const float* bp2 = (const float*)d_in[12];
    const float* Wq1 = (const float*)d_in[13];
    const float* bq1 = (const float*)d_in[14];
    const float* g1  = (const float*)d_in[15];
    const float* be1 = (const float*)d_in[16];
    const float* Wq2 = (const float*)d_in[17];
    const float* bq2 = (const float*)d_in[18];
    const float* g2  = (const float*)d_in[19];
    const float* be2 = (const float*)d_in[20];
    const float* Wq3 = (const float*)d_in[21];
    const float* bq3 = (const float*)d_in[22];

    tables_kernel<<<1, 64>>>(W1, b1, W2, b2, Wa, ba, Wp1, bp1, Wp2, bp2);
    class_kernel<<<64, 256>>>(labels);
    qsim_kernel<<<1024, 256>>>(noise, qp);

    cudaFuncSetAttribute(mlp_kernel, cudaFuncAttributeMaxDynamicSharedMemorySize, SMEM_C);
    mlp_kernel<<<256, MLP_THREADS, SMEM_C>>>(Wq1, bq1, g1, be1, Wq2, bq2, g2, be2, Wq3, bq3,
                                             (float*)d_out);
}

// round 13
// speedup vs baseline: 1.3201x; 1.0380x over previous
#include <cuda_runtime.h>
#include <math.h>

#define B_TOTAL 16384
#define PI_F 3.14159265358979323846f

typedef unsigned long long u64;

// ---------------- packed f32x2 helpers (exact fp32, 2 per issue) ----------------
__device__ __forceinline__ u64 pk(float lo, float hi) {
    u64 d; asm("mov.b64 %0, {%1, %2};" : "=l"(d) : "f"(lo), "f"(hi)); return d;
}
__device__ __forceinline__ void upk(u64 v, float& lo, float& hi) {
    asm("mov.b64 {%0, %1}, %2;" : "=f"(lo), "=f"(hi) : "l"(v));
}
__device__ __forceinline__ u64 f2fma(u64 a, u64 b, u64 c) {
    u64 d; asm("fma.rn.f32x2 %0, %1, %2, %3;" : "=l"(d) : "l"(a), "l"(b), "l"(c)); return d;
}

// ---------------- scratch ----------------
__device__ float g_ang[10 * 16];
__device__ float g_cpost[10 * 32];
__device__ int   g_cls[B_TOTAL];
__device__ float g_qf[B_TOTAL * 256];

__device__ __forceinline__ float lrelu(float x) { return x > 0.f ? x : 0.2f * x; }

// ---------------- Kernel A1: per-class tables ----------------
__global__ void tables_kernel(const float* __restrict__ W1, const float* __restrict__ b1,
                              const float* __restrict__ W2, const float* __restrict__ b2,
                              const float* __restrict__ Wa, const float* __restrict__ ba,
                              const float* __restrict__ Wp1, const float* __restrict__ bp1,
                              const float* __restrict__ Wp2, const float* __restrict__ bp2)
{
    __shared__ float h[64], p1[32];
    int t = threadIdx.x;
    for (int c = 0; c < 10; c++) {
        float hv = 0.f;
        if (t < 64) { hv = lrelu(W1[t * 10 + c] + b1[t]); h[t] = hv; }
        __syncthreads();
        float acc = 0.f;
        if (t < 64) {
            acc = b2[t];
            for (int k = 0; k < 64; k++) acc = fmaf(W2[t * 64 + k], h[k], acc);
            acc = lrelu(acc);
        }
        __syncthreads();
        if (t < 64) h[t] = hv + acc;
        if (t < 32) p1[t] = lrelu(Wp1[t * 10 + c] + bp1[t]);
        __syncthreads();
        if (t < 16) {
            float a = ba[t];
            for (int k = 0; k < 64; k++) a = fmaf(Wa[t * 64 + k], h[k], a);
            g_ang[c * 16 + t] = tanhf(a) * PI_F;
        }
        if (t < 32) {
            float a = bp2[t];
            for (int k = 0; k < 32; k++) a = fmaf(Wp2[t * 32 + k], p1[k], a);
            g_cpost[c * 32 + t] = lrelu(a);
        }
        __syncthreads();
    }
}

// ---------------- Kernel A2: class ids ----------------
__global__ void class_kernel(const float* __restrict__ labels)
{
    int b = blockIdx.x * 256 + threadIdx.x;
    const float* l = labels + b * 10;
    int c = 0; float best = l[0];
#pragma unroll
    for (int j = 1; j < 10; j++) { float v = l[j]; if (v > best) { best = v; c = j; } }
    g_cls[b] = c;
}

// ---------------- Kernel B: qsim, 4 samples/warp, 8 lanes/sample, 32 amps/lane -----
// lane = s*8 + L. Amp idx = L*32 + j, wire w <-> bit (7-w) of idx.
// Wires 0..2 -> L bits 2..0 (shfl masks 4,2,1). Wires 3..7 -> j bits 4..0 (local).
// Depth-0 RY folded into per-qubit vectors; state re-expanded per generator.
// Depths 1..5 in shear form (global cos product cancels in probs/max epilogue).
// CZ chain = sign-bit XOR; final CZ skipped.
__global__ __launch_bounds__(256) void qsim_kernel(const float* __restrict__ noise,
                                                   const float* __restrict__ qp)
{
    __shared__ float2 cs[192];             // cos/sin 0.5*w (depth-0 fold)
    __shared__ float  ts[192];             // tan 0.5*w (shear coefficients)
    __shared__ float  psi[32][8][2][2];    // base per-qubit vectors (32 samples/CTA)
    __shared__ float  psi2[32][8][2][2];   // per-gen rotated vectors
    int tid = threadIdx.x;
    if (tid < 192) {
        float w = qp[tid];
        float sw, cw; sincosf(0.5f * w, &sw, &cw);
        cs[tid] = make_float2(cw, sw);
        ts[tid] = sw / cw;
    }
    int warp = tid >> 5, lane = tid & 31;
    int s = lane >> 3, L = lane & 7;
    int sl = warp * 4 + s;
    int b = blockIdx.x * 32 + sl;

    {   // one thread per (sample, qubit): RZ(theta)*RY(ang+noise)|0>
        int slq = tid >> 3, q = tid & 7;
        int bb = blockIdx.x * 32 + slq;
        int c = g_cls[bb];
        float t = 0.5f * (g_ang[c * 16 + q] + noise[bb * 8 + q]);
        float st, ct; sincosf(t, &st, &ct);
        float th = 0.5f * g_ang[c * 16 + 8 + q];
        float sth, cth; sincosf(th, &sth, &cth);
        psi[slq][q][0][0] = ct * cth;
        psi[slq][q][0][1] = -ct * sth;
        psi[slq][q][1][0] = st * cth;
        psi[slq][q][1][1] = st * sth;
    }
    __syncthreads();

    // CZ-chain sign mask: bit j = parity(popc(idx & idx>>1 & 0x7F)), idx = L*32+j
    unsigned M = 0;
#pragma unroll
    for (int j = 0; j < 32; j++) {
        int idx = L * 32 + j;
        M |= ((unsigned)(__popc(idx & (idx >> 1) & 0x7F) & 1)) << j;
    }

    for (int g = 0; g < 4; g++) {
        // fold depth-0 RY (warp-local: tid>>3 covers this warp's 4 samples x 8 qubits)
        {
            int slq = tid >> 3, q = tid & 7;
            float2 w0 = cs[g * 48 + q];
            float cg = w0.x, sg = w0.y;
            float v0r = psi[slq][q][0][0], v0i = psi[slq][q][0][1];
            float v1r = psi[slq][q][1][0], v1i = psi[slq][q][1][1];
            psi2[slq][q][0][0] = cg * v0r - sg * v1r;
            psi2[slq][q][0][1] = cg * v0i - sg * v1i;
            psi2[slq][q][1][0] = sg * v0r + cg * v1r;
            psi2[slq][q][1][1] = sg * v0i + cg * v1i;
        }
        __syncwarp();

        // base over wires 0..2 (L bits 2..0)
        float br = 1.f, bi = 0.f;
#pragma unroll
        for (int w = 0; w < 3; w++) {
            int bit = (L >> (2 - w)) & 1;
            float pr = psi2[sl][w][bit][0], pi = psi2[sl][w][bit][1];
            float nr = br * pr - bi * pi;
            float ni = br * pi + bi * pr;
            br = nr; bi = ni;
        }
        // doubling over wires 7,6,5,4 (j bits 0..3) -> 16 intermediates
        float xr[16], xi[16];
        xr[0] = br; xi[0] = bi;
#pragma unroll
        for (int stage = 0; stage < 4; stage++) {
            int w = 7 - stage;
            int len = 1 << stage;
            float p0r = psi2[sl][w][0][0], p0i = psi2[sl][w][0][1];
            float p1r = psi2[sl][w][1][0], p1i = psi2[sl][w][1][1];
#pragma unroll
            for (int k = 0; k < 8; k++) {
                if (k < len) {
                    float t1r = xr[k] * p1r - xi[k] * p1i;
                    float t1i = xr[k] * p1i + xi[k] * p1r;
                    float t0r = xr[k] * p0r - xi[k] * p0i;
                    float t0i = xr[k] * p0i + xi[k] * p0r;
                    xr[k + len] = t1r; xi[k + len] = t1i;
                    xr[k] = t0r; xi[k] = t0i;
                }
            }
        }
        // wire 3 (j bit 4) applied at pack: a[j]=x16[j]*p3[0], a[j+16]=x16[j]*p3[1]
        u64 a[32];
        {
            float p0r = psi2[sl][3][0][0], p0i = psi2[sl][3][0][1];
            float p1r = psi2[sl][3][1][0], p1i = psi2[sl][3][1][1];
#pragma unroll
            for (int j = 0; j < 16; j++) {
                a[j]      = pk(xr[j] * p0r - xi[j] * p0i, xr[j] * p0i + xi[j] * p0r);
                a[j + 16] = pk(xr[j] * p1r - xi[j] * p1i, xr[j] * p1i + xi[j] * p1r);
            }
        }
#pragma unroll
        for (int j = 0; j < 32; j++)
            if (M & (1u << j)) a[j] ^= 0x8000000080000000ULL;  // depth-0 CZ

        // depths 1..5: shear form
        for (int d = 1; d < 6; d++) {
            const float* tsd = &ts[g * 48 + d * 8];
            // wires 0..2: cross-lane, masks 4,2,1 (stay within 8-lane group)
#pragma unroll
            for (int w = 0; w < 3; w++) {
                float tv = tsd[w];
                int m = 4 >> w;
                float sg = (L & m) ? tv : -tv;
                u64 sgp = pk(sg, sg);
#pragma unroll
                for (int j = 0; j < 32; j++) {
                    u64 part = __shfl_xor_sync(0xffffffffu, a[j], m);
                    a[j] = f2fma(sgp, part, a[j]);
                }
            }
            // wire 3: step 16
            {
                float tv = tsd[3];
                u64 tp = pk(tv, tv), mtp = pk(-tv, -tv);
#pragma unroll
                for (int j0 = 0; j0 < 16; j0++) {
                    int j1 = j0 + 16;
                    u64 v0 = a[j0], v1 = a[j1];
                    a[j0] = f2fma(mtp, v1, v0);
                    a[j1] = f2fma(tp, v0, v1);
                }
            }
            // wire 4: step 8
            {
                float tv = tsd[4];
                u64 tp = pk(tv, tv), mtp = pk(-tv, -tv);
#pragma unroll
                for (int t = 0; t < 16; t++) {
                    int j0 = (t & 7) | ((t >> 3) << 4);   // 0..7, 16..23
                    int j1 = j0 + 8;
                    u64 v0 = a[j0], v1 = a[j1];
                    a[j0] = f2fma(mtp, v1, v0);
                    a[j1] = f2fma(tp, v0, v1);
                }
            }
            // wire 5: step 4
            {
                float tv = tsd[5];
                u64 tp = pk(tv, tv), mtp = pk(-tv, -tv);
#pragma unroll
                for (int t = 0; t < 16; t++) {
                    int j0 = (t & 3) | ((t >> 2) << 3);   // 0..3, 8..11, 16..19, 24..27
                    int j1 = j0 + 4;
                    u64 v0 = a[j0], v1 = a[j1];
                    a[j0] = f2fma(mtp, v1, v0);
                    a[j1] = f2fma(tp, v0, v1);
                }
            }
            // wire 6: step 2
            {
                float tv = tsd[6];
                u64 tp = pk(tv, tv), mtp = pk(-tv, -tv);
#pragma unroll
                for (int t = 0; t < 16; t++) {
                    int j0 = (t & 1) | ((t >> 1) << 2);   // 0,1,4,5,...
                    int j1 = j0 + 2;
                    u64 v0 = a[j0], v1 = a[j1];
                    a[j0] = f2fma(mtp, v1, v0);
                    a[j1] = f2fma(tp, v0, v1);
                }
            }
            // wire 7: step 1
            {
                float tv = tsd[7];
                u64 tp = pk(tv, tv), mtp = pk(-tv, -tv);
#pragma unroll
                for (int t = 0; t < 16; t++) {
                    int j0 = t << 1, j1 = j0 + 1;
                    u64 v0 = a[j0], v1 = a[j1];
                    a[j0] = f2fma(mtp, v1, v0);
                    a[j1] = f2fma(tp, v0, v1);
                }
            }
            if (d < 5) {
#pragma unroll
                for (int j = 0; j < 32; j++)
                    if (M & (1u << j)) a[j] ^= 0x8000000080000000ULL;
            }
        }

        // epilogue: p0 = idx<64 -> lanes L<2; normalize by max over those 64
        float p[32];
#pragma unroll
        for (int j = 0; j < 32; j++) {
            float r, i; upk(a[j], r, i);
            p[j] = fmaf(r, r, i * i);
        }
        float mx = p[0];
#pragma unroll
        for (int j = 1; j < 32; j++) mx = fmaxf(mx, p[j]);
        mx = fmaxf(mx, __shfl_xor_sync(0xffffffffu, mx, 1));  // L0 <-> L1 (same sample)
        if (L < 2) {
            float inv = 1.f / mx;
            float* dst = &g_qf[b * 256 + g * 64 + L * 32];
#pragma unroll
            for (int j = 0; j < 32; j += 4)
                *(float4*)(dst + j) = make_float4(p[j] * inv, p[j + 1] * inv,
                                                 p[j + 2] * inv, p[j + 3] * inv);
        }
        __syncwarp();  // psi2 reused next gen
    }
}

// ---------------- Kernel C: fused MLP 288->128(LN)->128(LN)->64 tanh ----------------
// 64 samples/CTA, 512 threads (16 warps), 2 samples x 8 outputs per thread, f32x2.
// Weight chunks double-buffered: prefetch chunk c+1 in registers during compute c.
#define XS_STRIDE 292
#define H_STRIDE  132
#define NS 64
#define MLP_THREADS 512
#define WBUF 8192
#define SMEM_C ((NS * XS_STRIDE + NS * H_STRIDE + 2 * WBUF) * 4)

__global__ __launch_bounds__(MLP_THREADS) void mlp_kernel(
    const float* __restrict__ Wq1, const float* __restrict__ bq1,
    const float* __restrict__ g1,  const float* __restrict__ be1,
    const float* __restrict__ Wq2, const float* __restrict__ bq2,
    const float* __restrict__ g2,  const float* __restrict__ be2,
    const float* __restrict__ Wq3, const float* __restrict__ bq3,
    float* __restrict__ out)
{
    extern __shared__ float sm[];
    float* xs  = sm;                        // 64 x 292 (reused as h2, stride 132)
    float* h1  = sm + NS * XS_STRIDE;       // 64 x 132
    float* wcb = h1 + NS * H_STRIDE;        // 2 x WBUF weight buffers
    int tid = threadIdx.x, warp = tid >> 5, lane = tid & 31;
    int b0 = blockIdx.x * NS;
    int s1 = lane, s2 = lane + 32;

    for (int i = tid; i < NS * 64; i += MLP_THREADS) {
        int ss = i >> 6, k4 = (i & 63) << 2;
        *(float4*)&xs[ss * XS_STRIDE + k4] = *(const float4*)&g_qf[(b0 + ss) * 256 + k4];
    }
    for (int i = tid; i < NS * 8; i += MLP_THREADS) {
        int ss = i >> 3, k4 = (i & 7) << 2;
        *(float4*)&xs[ss * XS_STRIDE + 256 + k4] = *(const float4*)&g_cpost[g_cls[b0 + ss] * 32 + k4];
    }

    int ob = warp * 8;  // 16 warps x 8 outputs = 128
    // ---- layer 1: 288 -> 128 (6 chunks of 48 k, double-buffered) ----
    u64 aA[8], aB[8];
#pragma unroll
    for (int i = 0; i < 8; i++) { float bv = bq1[ob + i]; aA[i] = pk(bv, 0.f); aB[i] = pk(bv, 0.f); }
    // stage chunk 0 into buffer 0
#pragma unroll
    for (int r = 0; r < 3; r++) {
        int i = tid * 4 + r * 2048;
        *(float4*)&wcb[i] = *(const float4*)&Wq1[(i / 48) * 288 + (i % 48)];
    }
    __syncthreads();
    for (int ch = 0; ch < 6; ch++) {
        float4 pre[3];
        if (ch < 5) {
#pragma unroll
            for (int r = 0; r < 3; r++) {
                int i = tid * 4 + r * 2048;
                pre[r] = *(const float4*)&Wq1[(i / 48) * 288 + (ch + 1) * 48 + (i % 48)];
            }
        }
        const float* cw = &wcb[(ch & 1) * WBUF];
        const ulonglong2* xrA = (const ulonglong2*)&xs[s1 * XS_STRIDE + ch * 48];
        const ulonglong2* xrB = (const ulonglong2*)&xs[s2 * XS_STRIDE + ch * 48];
#pragma unroll
        for (int kk = 0; kk < 12; kk++) {
            ulonglong2 xa = xrA[kk], xb = xrB[kk];
#pragma unroll
            for (int i = 0; i < 8; i++) {
                ulonglong2 w = ((const ulonglong2*)&cw[(ob + i) * 48])[kk];
                aA[i] = f2fma(w.x, xa.x, aA[i]);
                aA[i] = f2fma(w.y, xa.y, aA[i]);
                aB[i] = f2fma(w.x, xb.x, aB[i]);
                aB[i] = f2fma(w.y, xb.y, aB[i]);
            }
        }
        if (ch < 5) {
            float* dw = &wcb[((ch + 1) & 1) * WBUF];
#pragma unroll
            for (int r = 0; r < 3; r++) {
                int i = tid * 4 + r * 2048;
                *(float4*)&dw[i] = pre[r];
            }
        }
        __syncthreads();
    }
#pragma unroll
    for (int i = 0; i < 8; i++) {
        float lo, hi;
        upk(aA[i], lo, hi); h1[s1 * H_STRIDE + ob + i] = lrelu(lo + hi);
        upk(aB[i], lo, hi); h1[s2 * H_STRIDE + ob + i] = lrelu(lo + hi);
    }
    __syncthreads();

    // ---- LN1 (16 warps x 4 samples) ----
    {
        float gv[4], bev[4];
#pragma unroll
        for (int r = 0; r < 4; r++) { gv[r] = g1[lane + 32 * r]; bev[r] = be1[lane + 32 * r]; }
        int s0 = warp * 4;
        for (int ss = s0; ss < s0 + 4; ss++) {
            float v[4]; float sum = 0.f, sq = 0.f;
#pragma unroll
            for (int r = 0; r < 4; r++) {
                v[r] = h1[ss * H_STRIDE + lane + 32 * r];
                sum += v[r]; sq = fmaf(v[r], v[r], sq);
            }
#pragma unroll
            for (int off = 16; off; off >>= 1) {
                sum += __shfl_xor_sync(0xffffffffu, sum, off);
                sq  += __shfl_xor_sync(0xffffffffu, sq, off);
            }
            float mu = sum * (1.f / 128.f);
            float var = sq * (1.f / 128.f) - mu * mu;
            float rs = rsqrtf(var + 1e-5f);
#pragma unroll
            for (int r = 0; r < 4; r++)
                h1[ss * H_STRIDE + lane + 32 * r] = (v[r] - mu) * rs * gv[r] + bev[r];
        }
    }
    __syncthreads();

    // ---- layer 2: 128 -> 128 (2 chunks of 64 k, double-buffered) ----
    float* h2 = xs;  // reuse, stride H_STRIDE
#pragma unroll
    for (int i = 0; i < 8; i++) { float bv = bq2[ob + i]; aA[i] = pk(bv, 0.f); aB[i] = pk(bv, 0.f); }
    // stage chunk 0 into buffer 0
#pragma unroll
    for (int r = 0; r < 4; r++) {
        int i = tid * 4 + r * 2048;
        *(float4*)&wcb[i] = *(const float4*)&Wq2[(i >> 6) * 128 + (i & 63)];
    }
    __syncthreads();
    for (int ch = 0; ch < 2; ch++) {
        float4 pre[4];
        if (ch < 1) {
#pragma unroll
            for (int r = 0; r < 4; r++) {
                int i = tid * 4 + r * 2048;
                pre[r] = *(const float4*)&Wq2[(i >> 6) * 128 + 64 + (i & 63)];
            }
        }
        const float* cw = &wcb[(ch & 1) * WBUF];
        const ulonglong2* xrA = (const ulonglong2*)&h1[s1 * H_STRIDE + ch * 64];
        const ulonglong2* xrB = (const ulonglong2*)&h1[s2 * H_STRIDE + ch * 64];
#pragma unroll
        for (int kk = 0; kk < 16; kk++) {
            ulonglong2 xa = xrA[kk], xb = xrB[kk];
#pragma unroll
            for (int i = 0; i < 8; i++) {
                ulonglong2 w = ((const ulonglong2*)&cw[(ob + i) * 64])[kk];
                aA[i] = f2fma(w.x, xa.x, aA[i]);
                aA[i] = f2fma(w.y, xa.y, aA[i]);
                aB[i] = f2fma(w.x, xb.x, aB[i]);
                aB[i] = f2fma(w.y, xb.y, aB[i]);
            }
        }
        if (ch < 1) {
            float* dw = &wcb[WBUF];
#pragma unroll
            for (int r = 0; r < 4; r++) {
                int i = tid * 4 + r * 2048;
                *(float4*)&dw[i] = pre[r];
            }
        }
        __syncthreads();
    }
#pragma unroll
    for (int i = 0; i < 8; i++) {
        float lo, hi;
        upk(aA[i], lo, hi); h2[s1 * H_STRIDE + ob + i] = lrelu(lo + hi);
        upk(aB[i], lo, hi); h2[s2 * H_STRIDE + ob + i] = lrelu(lo + hi);
    }
    __syncthreads();

    // ---- LN2 ----
    {
        float gv[4], bev[4];
#pragma unroll
        for (int r = 0; r < 4; r++) { gv[r] = g2[lane + 32 * r]; bev[r] = be2[lane + 32 * r]; }
        int s0 = warp * 4;
        for (int ss = s0; ss < s0 + 4; ss++) {
            float v[4]; float sum = 0.f, sq = 0.f;
#pragma unroll
            for (int r = 0; r < 4; r++) {
                v[r] = h2[ss * H_STRIDE + lane + 32 * r];
                sum += v[r]; sq = fmaf(v[r], v[r], sq);
            }
#pragma unroll
            for (int off = 16; off; off >>= 1) {
                sum += __shfl_xor_sync(0xffffffffu, sum, off);
                sq  += __shfl_xor_sync(0xffffffffu, sq, off);
            }
            float mu = sum * (1.f / 128.f);
            float var = sq * (1.f / 128.f) - mu * mu;
            float rs = rsqrtf(var + 1e-5f);
#pragma unroll
            for (int r = 0; r < 4; r++)
                h2[ss * H_STRIDE + lane + 32 * r] = (v[r] - mu) * rs * gv[r] + bev[r];
        }
    }

    // ---- layer 3: 128 -> 64, tanh ----
    int ob3 = warp * 4;  // 16 warps x 4 outputs = 64
    u64 cA[4], cB[4];
#pragma unroll
    for (int i = 0; i < 4; i++) { float bv = bq3[ob3 + i]; cA[i] = pk(bv, 0.f); cB[i] = pk(bv, 0.f); }
    __syncthreads();
#pragma unroll
    for (int r = 0; r < 4; r++) {
        int i = tid * 4 + r * 2048;
        *(float4*)&wcb[i] = *(const float4*)&Wq3[i];
    }
    __syncthreads();
    {
        const ulonglong2* xrA = (const ulonglong2*)&h2[s1 * H_STRIDE];
        const ulonglong2* xrB = (const ulonglong2*)&h2[s2 * H_STRIDE];
#pragma unroll
        for (int kk = 0; kk < 32; kk++) {
            ulonglong2 xa = xrA[kk], xb = xrB[kk];
#pragma unroll
            for (int i = 0; i < 4; i++) {
                ulonglong2 w = ((const ulonglong2*)&wcb[(ob3 + i) * 128])[kk];
                cA[i] = f2fma(w.x, xa.x, cA[i]);
                cA[i] = f2fma(w.y, xa.y, cA[i]);
                cB[i] = f2fma(w.x, xb.x, cB[i]);
                cB[i] = f2fma(w.y, xb.y, cB[i]);
            }
        }
    }
    {
        float oA[4], oB[4];
#pragma unroll
        for (int i = 0; i < 4; i++) {
            float lo, hi;
            upk(cA[i], lo, hi); oA[i] = tanhf(lo + hi);
            upk(cB[i], lo, hi); oB[i] = tanhf(lo + hi);
        }
        *(float4*)&out[(b0 + s1) * 64 + ob3] = make_float4(oA[0], oA[1], oA[2], oA[3]);
        *(float4*)&out[(b0 + s2) * 64 + ob3] = make_float4(oB[0], oB[1], oB[2], oB[3]);
    }
}

// ---------------- launch (serial, single stream) ----------------
extern "C" void kernel_launch(void* const* d_in, const int* in_sizes, int n_in,
                              void* d_out, int out_size)
{
    const float* noise  = (const float*)d_in[0];
    const float* labels = (const float*)d_in[1];
    const float* qp     = (const float*)d_in[2];
    const float* W1  = (const float*)d_in[3];
    const float* b1  = (const float*)d_in[4];
    const float* W2  = (const float*)d_in[5];
    const float* b2  = (const float*)d_in[6];
    const float* Wa  = (const float*)d_in[7];
    const float* ba  = (const float*)d_in[8];
    const float* Wp1 = (const float*)d_in[9];
    const float* bp1 = (const float*)d_in[10];
    const float* Wp2 = (const float*)d_in[11];
    const float* bp2 = (const float*)d_in[12];
    const float* Wq1 = (const float*)d_in[13];
    const float* bq1 = (const float*)d_in[14];
    const float* g1  = (const float*)d_in[15];
    const float* be1 = (const float*)d_in[16];
    const float* Wq2 = (const float*)d_in[17];
    const float* bq2 = (const float*)d_in[18];
    const float* g2  = (const float*)d_in[19];
    const float* be2 = (const float*)d_in[20];
    const float* Wq3 = (const float*)d_in[21];
    const float* bq3 = (const float*)d_in[22];

    tables_kernel<<<1, 64>>>(W1, b1, W2, b2, Wa, ba, Wp1, bp1, Wp2, bp2);
    class_kernel<<<64, 256>>>(labels);
    qsim_kernel<<<512, 256>>>(noise, qp);

    cudaFuncSetAttribute(mlp_kernel, cudaFuncAttributeMaxDynamicSharedMemorySize, SMEM_C);
    mlp_kernel<<<256, MLP_THREADS, SMEM_C>>>(Wq1, bq1, g1, be1, Wq2, bq2, g2, be2, Wq3, bq3,
                                             (float*)d_out);
}